// round 1
// baseline (speedup 1.0000x reference)
#include <cuda_runtime.h>
#include <math.h>

// Problem constants
#define B_    8
#define CIN   256
#define MID   128
#define Hh    128
#define Ww    256
#define Kk    19
#define HW    (Hh*Ww)          // 32768
#define EPSBN 1e-5f

// Scratch (device globals: allocation-free)
__device__ float g_x[B_ * MID * HW];          // conv3x3+BN+ReLU output: 128 MB
__device__ float g_g[B_ * Kk * 4 * HW];       // softmax guidance: ~80 MB
__device__ float g_h[B_ * Kk * HW];           // ping-pong h buffer: ~20 MB

// ---------------------------------------------------------------------------
// Kernel 1: conv3x3 (pad 1, no bias) + BatchNorm(inference) + ReLU
// Output tile per block: 64 MID x 1 row x 64 W.  blockDim (16,16)=256.
// Each thread: 4 mid x 4 w accumulators.
// ---------------------------------------------------------------------------
#define CCHUNK 8
__global__ __launch_bounds__(256) void conv3x3_bn_relu_kernel(
    const float* __restrict__ feats,   // [B][CIN][H][W]
    const float* __restrict__ w1,      // [MID][CIN][3][3]
    const float* __restrict__ gamma,
    const float* __restrict__ beta,
    const float* __restrict__ mean,
    const float* __restrict__ var)
{
    __shared__ __align__(16) float sW[CCHUNK*9][68];   // [k][mid], padded
    __shared__ __align__(16) float sF[3][CCHUNK][72];  // [dy][cin][w], padded

    const int tx = threadIdx.x;      // 0..15 -> w group (4 w each)
    const int ty = threadIdx.y;      // 0..15 -> mid group (4 mid each)
    const int tid = ty * 16 + tx;

    const int wt  = blockIdx.x & 3;
    const int h0  = blockIdx.x >> 2;        // output row
    const int mid0 = (blockIdx.y & 1) * 64;
    const int b    = blockIdx.y >> 1;
    const int w0   = wt * 64;

    float acc[4][4];
#pragma unroll
    for (int i = 0; i < 4; i++)
#pragma unroll
        for (int j = 0; j < 4; j++) acc[i][j] = 0.f;

    for (int c0 = 0; c0 < CIN; c0 += CCHUNK) {
        __syncthreads();
        // load weights chunk: 72 x 64
        for (int idx = tid; idx < CCHUNK*9*64; idx += 256) {
            int m = idx / (CCHUNK*9);
            int k = idx % (CCHUNK*9);
            sW[k][m] = w1[(mid0 + m) * (CIN*9) + c0*9 + k];
        }
        // load feats slab: 3 rows x CCHUNK cin x 66 w
        for (int idx = tid; idx < 3*CCHUNK*66; idx += 256) {
            int w  = idx % 66;
            int r  = idx / 66;
            int ci = r % CCHUNK;
            int dy = r / CCHUNK;
            int in_h = h0 - 1 + dy;
            int in_w = w0 - 1 + w;
            float v = 0.f;
            if ((unsigned)in_h < (unsigned)Hh && (unsigned)in_w < (unsigned)Ww)
                v = feats[((b*CIN + c0 + ci) * Hh + in_h) * Ww + in_w];
            sF[dy][ci][w] = v;
        }
        __syncthreads();

#pragma unroll
        for (int ci = 0; ci < CCHUNK; ci++) {
            // 6 input columns per dy covering dx 0..2 + 4 outputs
            float f6[3][6];
#pragma unroll
            for (int dy = 0; dy < 3; dy++) {
                float4 v0 = *(const float4*)&sF[dy][ci][4*tx];
                float2 v1 = *(const float2*)&sF[dy][ci][4*tx + 4];
                f6[dy][0]=v0.x; f6[dy][1]=v0.y; f6[dy][2]=v0.z; f6[dy][3]=v0.w;
                f6[dy][4]=v1.x; f6[dy][5]=v1.y;
            }
#pragma unroll
            for (int dy = 0; dy < 3; dy++) {
#pragma unroll
                for (int dx = 0; dx < 3; dx++) {
                    float4 a = *(const float4*)&sW[ci*9 + dy*3 + dx][4*ty];
                    float am[4] = {a.x, a.y, a.z, a.w};
#pragma unroll
                    for (int mi = 0; mi < 4; mi++)
#pragma unroll
                        for (int wi = 0; wi < 4; wi++)
                            acc[mi][wi] = fmaf(am[mi], f6[dy][dx+wi], acc[mi][wi]);
                }
            }
        }
    }

    // BN + ReLU + store
#pragma unroll
    for (int mi = 0; mi < 4; mi++) {
        int mid = mid0 + 4*ty + mi;
        float invv = gamma[mid] / sqrtf(var[mid] + EPSBN);
        float bias = beta[mid] - mean[mid] * invv;
        float4 o;
        o.x = fmaxf(acc[mi][0]*invv + bias, 0.f);
        o.y = fmaxf(acc[mi][1]*invv + bias, 0.f);
        o.z = fmaxf(acc[mi][2]*invv + bias, 0.f);
        o.w = fmaxf(acc[mi][3]*invv + bias, 0.f);
        *(float4*)&g_x[((b*MID + mid) * Hh + h0) * Ww + w0 + 4*tx] = o;
    }
}

// ---------------------------------------------------------------------------
// Kernel 2: conv1x1 (MID->K*4) + bias + softmax over the 4 directions
// Block: 32 pixels, blockDim (32,8). Thread owns up to 3 k values.
// ---------------------------------------------------------------------------
__global__ __launch_bounds__(256) void conv1x1_softmax_kernel(
    const float* __restrict__ w2,    // [K*4][MID]
    const float* __restrict__ b2)    // [K*4]
{
    __shared__ __align__(16) float sX[32][68];     // [px][m-half]
    __shared__ __align__(16) float sW2[Kk*4][64];  // [kd][m-half]

    const int px = threadIdx.x;          // 0..31
    const int ty = threadIdx.y;          // 0..7
    const int tid = ty*32 + px;
    const int p0 = blockIdx.x * 32;      // pixel offset within plane
    const int b  = blockIdx.y;

    const int nk = (ty < 3) ? 3 : 2;
    float acc[3][4];
#pragma unroll
    for (int i = 0; i < 3; i++)
#pragma unroll
        for (int d = 0; d < 4; d++) acc[i][d] = 0.f;

    for (int half = 0; half < 2; half++) {
        __syncthreads();
        for (int idx = tid; idx < 64*32; idx += 256) {
            int m = idx >> 5, p = idx & 31;
            sX[p][m] = g_x[(b*MID + half*64 + m) * HW + p0 + p];
        }
        for (int idx = tid; idx < Kk*4*64; idx += 256) {
            int kd = idx >> 6, m = idx & 63;
            sW2[kd][m] = w2[kd * MID + half*64 + m];
        }
        __syncthreads();

        for (int m = 0; m < 64; m += 4) {
            float4 xv = *(const float4*)&sX[px][m];
#pragma unroll
            for (int ki = 0; ki < 3; ki++) {
                if (ki >= nk) break;
                int k = ty + 8*ki;
#pragma unroll
                for (int d = 0; d < 4; d++) {
                    float4 wv = *(const float4*)&sW2[4*k + d][m];
                    acc[ki][d] = fmaf(xv.x, wv.x, acc[ki][d]);
                    acc[ki][d] = fmaf(xv.y, wv.y, acc[ki][d]);
                    acc[ki][d] = fmaf(xv.z, wv.z, acc[ki][d]);
                    acc[ki][d] = fmaf(xv.w, wv.w, acc[ki][d]);
                }
            }
        }
    }

#pragma unroll
    for (int ki = 0; ki < 3; ki++) {
        if (ki >= nk) break;
        int k = ty + 8*ki;
        float v[4];
#pragma unroll
        for (int d = 0; d < 4; d++) v[d] = acc[ki][d] + b2[4*k + d];
        float mx = fmaxf(fmaxf(v[0], v[1]), fmaxf(v[2], v[3]));
        float e[4], s = 0.f;
#pragma unroll
        for (int d = 0; d < 4; d++) { e[d] = expf(v[d] - mx); s += e[d]; }
        float inv = 1.f / s;
#pragma unroll
        for (int d = 0; d < 4; d++)
            g_g[((b*Kk + k)*4 + d) * HW + p0 + px] = e[d] * inv;
    }
}

// ---------------------------------------------------------------------------
// Kernel 3: one propagation step
// h_out = (1 - sum g) * h + g0*left + g1*right + g2*up + g3*down
// ---------------------------------------------------------------------------
__global__ __launch_bounds__(256) void prop_step_kernel(
    const float* __restrict__ h_in, float* __restrict__ h_out)
{
    int idx = blockIdx.x * 256 + threadIdx.x;
    const int total = B_ * Kk * HW;
    if (idx >= total) return;

    int w  = idx & (Ww - 1);
    int hh = (idx >> 8) & (Hh - 1);
    int plane = idx >> 15;

    float h = h_in[idx];
    float l = (w > 0)      ? h_in[idx - 1]   : 0.f;
    float r = (w < Ww - 1) ? h_in[idx + 1]   : 0.f;
    float u = (hh > 0)     ? h_in[idx - Ww]  : 0.f;
    float d = (hh < Hh-1)  ? h_in[idx + Ww]  : 0.f;

    const float* gp = g_g + (size_t)plane * 4 * HW + (hh * Ww + w);
    float g0 = gp[0*HW], g1 = gp[1*HW], g2 = gp[2*HW], g3 = gp[3*HW];
    float selfw = 1.f - (g0 + g1 + g2 + g3);

    float agg = g0 * l;
    agg += g1 * r;
    agg += g2 * u;
    agg += g3 * d;
    h_out[idx] = selfw * h + agg;
}

// ---------------------------------------------------------------------------
// kernel_launch
// inputs: 0 feats, 1 logits, 2 w1, 3 gamma, 4 beta, 5 mean, 6 var, 7 w2, 8 b2
// ---------------------------------------------------------------------------
extern "C" void kernel_launch(void* const* d_in, const int* in_sizes, int n_in,
                              void* d_out, int out_size)
{
    const float* feats  = (const float*)d_in[0];
    const float* logits = (const float*)d_in[1];
    const float* w1     = (const float*)d_in[2];
    const float* gamma  = (const float*)d_in[3];
    const float* beta   = (const float*)d_in[4];
    const float* mean   = (const float*)d_in[5];
    const float* var    = (const float*)d_in[6];
    const float* w2     = (const float*)d_in[7];
    const float* b2     = (const float*)d_in[8];
    float* out = (float*)d_out;

    float* hbuf;
    cudaGetSymbolAddress((void**)&hbuf, g_h);

    // 1) conv3x3 + BN + ReLU
    {
        dim3 grid(Hh * (Ww/64), B_ * (MID/64));  // (512, 16)
        dim3 block(16, 16);
        conv3x3_bn_relu_kernel<<<grid, block>>>(feats, w1, gamma, beta, mean, var);
    }
    // 2) conv1x1 + bias + softmax -> g
    {
        dim3 grid(HW/32, B_);                    // (1024, 8)
        dim3 block(32, 8);
        conv1x1_softmax_kernel<<<grid, block>>>(w2, b2);
    }
    // 3) 4 propagation steps: logits -> hbuf -> out -> hbuf -> out
    {
        int total = B_ * Kk * HW;
        int blocks = (total + 255) / 256;
        prop_step_kernel<<<blocks, 256>>>(logits, hbuf);
        prop_step_kernel<<<blocks, 256>>>(hbuf, out);
        prop_step_kernel<<<blocks, 256>>>(out, hbuf);
        prop_step_kernel<<<blocks, 256>>>(hbuf, out);
    }
}

// round 3
// speedup vs baseline: 3.9553x; 3.9553x over previous
#include <cuda_runtime.h>
#include <math.h>

// ---------------------------------------------------------------------------
// Problem constants
// ---------------------------------------------------------------------------
#define B_    8
#define CIN   256
#define MID   128
#define Hh    128
#define Ww    256
#define Kk    19
#define HW    (Hh*Ww)          // 32768
#define EPSBN 1e-5f
#define HP    (Hh+2)           // 130
#define WP    (Ww+2)           // 258

// ---------------------------------------------------------------------------
// Scratch (device globals: allocation-free)
// ---------------------------------------------------------------------------
__device__ float g_ft[(size_t)B_ * HP * WP * CIN];   // tf32 bits, NHWC padded
__device__ float g_w1t[72 * MID * 32];               // tf32 bits, [s][mid][ci32]
__device__ float g_xT[(size_t)B_ * HW * MID];        // fp32 [b][pixel][mid]
__device__ float g_g[(size_t)B_ * Kk * 4 * HW];      // softmax guidance
__device__ float g_h[(size_t)B_ * Kk * HW];          // ping-pong h buffer

// ---------------------------------------------------------------------------
// Helpers
// ---------------------------------------------------------------------------
static __device__ __forceinline__ unsigned smem_u32(const void* p) {
    unsigned r;
    asm("{ .reg .u64 t; cvta.to.shared.u64 t, %1; cvt.u32.u64 %0, t; }"
        : "=r"(r) : "l"(p));
    return r;
}

static __device__ __forceinline__ void cp16(unsigned saddr, const void* gptr) {
    asm volatile("cp.async.cg.shared.global [%0], [%1], 16;"
                 :: "r"(saddr), "l"(gptr));
}

static __device__ __forceinline__ void ldsm4(unsigned* r, unsigned addr) {
    asm volatile("ldmatrix.sync.aligned.m8n8.x4.shared.b16 {%0,%1,%2,%3}, [%4];"
        : "=r"(r[0]), "=r"(r[1]), "=r"(r[2]), "=r"(r[3]) : "r"(addr));
}

static __device__ __forceinline__ void mma1688(float* c, const unsigned* a,
                                               const unsigned* b) {
    asm volatile(
        "mma.sync.aligned.m16n8k8.row.col.f32.tf32.tf32.f32 "
        "{%0,%1,%2,%3}, {%4,%5,%6,%7}, {%8,%9}, {%0,%1,%2,%3};"
        : "+f"(c[0]), "+f"(c[1]), "+f"(c[2]), "+f"(c[3])
        : "r"(a[0]), "r"(a[1]), "r"(a[2]), "r"(a[3]), "r"(b[0]), "r"(b[1]));
}

static __device__ __forceinline__ float tf32_rna(float v) {
    unsigned o;
    asm("cvt.rna.tf32.f32 %0, %1;" : "=r"(o) : "f"(v));
    return __uint_as_float(o);
}

// ---------------------------------------------------------------------------
// Kernel T1: feats NCHW -> padded NHWC (tf32-rounded). grid (HP, B), block (32,8)
// ---------------------------------------------------------------------------
__global__ __launch_bounds__(256) void transpose_pad_kernel(
    const float* __restrict__ feats)
{
    __shared__ float t[32][33];
    const int tx = threadIdx.x, ty = threadIdx.y;
    const int tid = ty * 32 + tx;
    const int hp = blockIdx.x, b = blockIdx.y;
    float* orow = g_ft + ((size_t)(b * HP + hp) * WP) * CIN;

    if (hp == 0 || hp == HP - 1) {
        for (int idx = tid; idx < WP * CIN; idx += 256) orow[idx] = 0.f;
        return;
    }
    if (tid < 256) { orow[tid] = 0.f; orow[(WP - 1) * CIN + tid] = 0.f; }

    const int h = hp - 1;
    for (int wt = 0; wt < 8; wt++) {
        for (int ct = 0; ct < 8; ct++) {
            const int w0 = wt * 32, c0 = ct * 32;
            __syncthreads();
#pragma unroll
            for (int j = 0; j < 4; j++) {
                int ci = c0 + ty + j * 8;
                t[ty + j * 8][tx] =
                    feats[(((size_t)b * CIN + ci) * Hh + h) * Ww + w0 + tx];
            }
            __syncthreads();
#pragma unroll
            for (int j = 0; j < 4; j++) {
                int w = w0 + ty + j * 8;
                orow[(size_t)(w + 1) * CIN + c0 + tx] = tf32_rna(t[tx][ty + j * 8]);
            }
        }
    }
}

// ---------------------------------------------------------------------------
// Kernel T2: w1 [MID][CIN][3][3] -> g_w1t[s][mid][ci32], s=(dy*3+dx)*8+cc
// ---------------------------------------------------------------------------
__global__ __launch_bounds__(256) void prep_w1t_kernel(const float* __restrict__ w1)
{
    int idx = blockIdx.x * 256 + threadIdx.x;
    if (idx >= 72 * MID * 32) return;
    int cw = idx & 31;
    int m  = (idx >> 5) & 127;
    int s  = idx >> 12;
    int dydx = s >> 3, cc = s & 7;
    int dy = dydx / 3, dx = dydx % 3;
    int ci = cc * 32 + cw;
    g_w1t[idx] = tf32_rna(w1[(((size_t)m * CIN + ci) * 3 + dy) * 3 + dx]);
}

// ---------------------------------------------------------------------------
// Kernel G: conv3x3 as tf32 mma.sync implicit GEMM + BN + ReLU epilogue.
// Per CTA: one (b,h) row. M=256 pixels, N=128 mid, K=2304.
// Super-stage t = (dy, ci32-chunk), 24 total. A(feats) tile loaded once per t
// (258 pixel rows x 32 k), the 3 dx taps are +1-row shifts; B(weights) 3 tiles.
// Warps: 4(m) x 2(n), warp tile 64x64, mma m16n8k8 tf32.
// smem stage: A 264*128=33792B + B 3*16384=49152B -> 82944B, double buffered.
// ---------------------------------------------------------------------------
#define A_ST   33792
#define B_ST   49152
#define STG    (A_ST + B_ST)     // 82944
#define CSMEM  (2 * STG)         // 165888

__global__ void __launch_bounds__(256) conv3x3_mma_kernel(
    const float* __restrict__ gamma, const float* __restrict__ beta,
    const float* __restrict__ mean,  const float* __restrict__ var)
{
    extern __shared__ __align__(1024) unsigned char smem_raw[];
    const unsigned sbase = smem_u32(smem_raw);
    const int tid = threadIdx.x;
    const int L = tid & 31, wid = tid >> 5;
    const int h = blockIdx.x, b = blockIdx.y;
    const int p0w = (wid >> 1) * 64;     // warp m-offset (pixels)
    const int n0w = (wid & 1) * 64;      // warp n-offset (mid)

    // fragment lane constants
    const int tr    = L & 7;
    const int arow  = ((L >> 3) & 1) * 8 + tr;  // A row-in-16
    const int ahalf = L >> 4;                   // A 16B-chunk half
    const int bchnk = (L >> 3) & 1;             // B chunk half
    const int bnrow = L >> 4;                   // B ntile-in-pair

    auto issue_loads = [&](int t, int buf) {
        const int dy = t >> 3, cc = t & 7;
        const unsigned Ab = sbase + buf * STG;
        const unsigned Bb = Ab + A_ST;
        const float* asrc = g_ft + ((size_t)(b * HP + h + dy) * WP) * CIN + cc * 32;
#pragma unroll
        for (int i = 0; i < 9; i++) {            // A: 258 rows x 8 chunks = 2064
            int g = tid + i * 256;
            if (g < 2064) {
                int row = g >> 3, c = g & 7;
                cp16(Ab + row * 128 + ((c ^ (row & 7)) << 4),
                     asrc + (size_t)row * CIN + c * 4);
            }
        }
        const size_t wbase = ((size_t)dy * 3 * 8 + cc) * 4096;
#pragma unroll
        for (int i = 0; i < 12; i++) {           // B: 3 x 128 rows x 8 chunks
            int g = tid + i * 256;
            int dxi = g >> 10, row = (g >> 3) & 127, c = g & 7;
            cp16(Bb + dxi * 16384 + row * 128 + ((c ^ (row & 7)) << 4),
                 g_w1t + wbase + (size_t)dxi * 8 * 4096 + row * 32 + c * 4);
        }
        asm volatile("cp.async.commit_group;");
    };

    float acc[4][8][4];
#pragma unroll
    for (int mi = 0; mi < 4; mi++)
#pragma unroll
        for (int ni = 0; ni < 8; ni++)
#pragma unroll
            for (int q = 0; q < 4; q++) acc[mi][ni][q] = 0.f;

    issue_loads(0, 0);

    for (int t = 0; t < 24; t++) {
        const int buf = t & 1;
        asm volatile("cp.async.wait_group 0;");
        __syncthreads();
        if (t < 23) issue_loads(t + 1, buf ^ 1);

        const unsigned Ab = sbase + buf * STG;
        const unsigned Bb = Ab + A_ST;
#pragma unroll
        for (int dx = 0; dx < 3; dx++) {
#pragma unroll
            for (int kk = 0; kk < 4; kk++) {
                unsigned a[4][4], bf[4][4];
#pragma unroll
                for (int mi = 0; mi < 4; mi++) {
                    int row = p0w + mi * 16 + arow + dx;
                    unsigned ad = Ab + row * 128 +
                        ((((kk << 1) + ahalf) ^ (row & 7)) << 4);
                    ldsm4(a[mi], ad);
                }
#pragma unroll
                for (int j = 0; j < 4; j++) {
                    int row = n0w + (2 * j + bnrow) * 8 + tr;
                    unsigned bd = Bb + dx * 16384 + row * 128 +
                        ((((kk << 1) + bchnk) ^ tr) << 4);
                    ldsm4(bf[j], bd);
                }
#pragma unroll
                for (int mi = 0; mi < 4; mi++)
#pragma unroll
                    for (int ni = 0; ni < 8; ni++)
                        mma1688(acc[mi][ni], a[mi], &bf[ni >> 1][(ni & 1) << 1]);
            }
        }
        __syncthreads();
    }

    // Epilogue: BN + ReLU -> g_xT[b][pixel][mid]
    const int midb = n0w + ((L & 3) << 1);
    float iv0[8], iv1[8], bb0[8], bb1[8];
#pragma unroll
    for (int ni = 0; ni < 8; ni++) {
        int m0 = midb + ni * 8;
        iv0[ni] = gamma[m0]     * rsqrtf(var[m0]     + EPSBN);
        iv1[ni] = gamma[m0 + 1] * rsqrtf(var[m0 + 1] + EPSBN);
        bb0[ni] = beta[m0]     - mean[m0]     * iv0[ni];
        bb1[ni] = beta[m0 + 1] - mean[m0 + 1] * iv1[ni];
    }
#pragma unroll
    for (int mi = 0; mi < 4; mi++) {
        int p0 = p0w + mi * 16 + (L >> 2);
        float* o = g_xT + ((size_t)b * HW + (size_t)h * Ww + p0) * MID;
#pragma unroll
        for (int ni = 0; ni < 8; ni++) {
            int m0 = midb + ni * 8;
            float2 u0, u1;
            u0.x = fmaxf(fmaf(acc[mi][ni][0], iv0[ni], bb0[ni]), 0.f);
            u0.y = fmaxf(fmaf(acc[mi][ni][1], iv1[ni], bb1[ni]), 0.f);
            u1.x = fmaxf(fmaf(acc[mi][ni][2], iv0[ni], bb0[ni]), 0.f);
            u1.y = fmaxf(fmaf(acc[mi][ni][3], iv1[ni], bb1[ni]), 0.f);
            *(float2*)(o + m0) = u0;
            *(float2*)(o + 8 * MID + m0) = u1;
        }
    }
}

// ---------------------------------------------------------------------------
// Kernel 2: conv1x1 (MID->K*4) + bias + softmax over 4 dirs. Reads g_xT.
// ---------------------------------------------------------------------------
__global__ __launch_bounds__(256) void conv1x1_softmax_kernel(
    const float* __restrict__ w2, const float* __restrict__ b2)
{
    __shared__ float sXT[128][33];   // [m][px]
    __shared__ float sW2[76][64];    // [kd][m-half]

    const int tid = threadIdx.x;
    const int p0 = blockIdx.x * 32, b = blockIdx.y;
    const float* xsrc = g_xT + ((size_t)b * HW + p0) * MID;

#pragma unroll
    for (int i = 0; i < 16; i++) {
        int idx = tid + i * 256;
        int p = idx >> 7, m = idx & 127;
        sXT[m][p] = xsrc[(size_t)p * MID + m];
    }

    const int px = tid & 31, ty = tid >> 5;
    const int nk = (ty < 3) ? 3 : 2;
    float acc[3][4];
#pragma unroll
    for (int i = 0; i < 3; i++)
#pragma unroll
        for (int d = 0; d < 4; d++) acc[i][d] = 0.f;

    for (int half = 0; half < 2; half++) {
        __syncthreads();
        for (int idx = tid; idx < 76 * 64; idx += 256) {
            int kd = idx >> 6, m = idx & 63;
            sW2[kd][m] = w2[kd * MID + half * 64 + m];
        }
        __syncthreads();
        for (int mm = 0; mm < 64; mm += 4) {
            const int m = half * 64 + mm;
            float x0 = sXT[m][px], x1 = sXT[m + 1][px];
            float x2 = sXT[m + 2][px], x3 = sXT[m + 3][px];
#pragma unroll
            for (int ki = 0; ki < 3; ki++) {
                if (ki >= nk) break;
                int k = ty + 8 * ki;
#pragma unroll
                for (int d = 0; d < 4; d++) {
                    float4 wv = *(const float4*)&sW2[4 * k + d][mm];
                    acc[ki][d] = fmaf(x0, wv.x, acc[ki][d]);
                    acc[ki][d] = fmaf(x1, wv.y, acc[ki][d]);
                    acc[ki][d] = fmaf(x2, wv.z, acc[ki][d]);
                    acc[ki][d] = fmaf(x3, wv.w, acc[ki][d]);
                }
            }
        }
    }

#pragma unroll
    for (int ki = 0; ki < 3; ki++) {
        if (ki >= nk) break;
        int k = ty + 8 * ki;
        float v[4];
#pragma unroll
        for (int d = 0; d < 4; d++) v[d] = acc[ki][d] + b2[4 * k + d];
        float mx = fmaxf(fmaxf(v[0], v[1]), fmaxf(v[2], v[3]));
        float e[4], sum = 0.f;
#pragma unroll
        for (int d = 0; d < 4; d++) { e[d] = expf(v[d] - mx); sum += e[d]; }
        float inv = 1.f / sum;
#pragma unroll
        for (int d = 0; d < 4; d++)
            g_g[(((size_t)b * Kk + k) * 4 + d) * HW + p0 + px] = e[d] * inv;
    }
}

// ---------------------------------------------------------------------------
// Kernel 3: one propagation step
// ---------------------------------------------------------------------------
__global__ __launch_bounds__(256) void prop_step_kernel(
    const float* __restrict__ h_in, float* __restrict__ h_out)
{
    int idx = blockIdx.x * 256 + threadIdx.x;
    const int total = B_ * Kk * HW;
    if (idx >= total) return;

    int w  = idx & (Ww - 1);
    int hh = (idx >> 8) & (Hh - 1);
    int plane = idx >> 15;

    float h = h_in[idx];
    float l = (w > 0)      ? h_in[idx - 1]  : 0.f;
    float r = (w < Ww - 1) ? h_in[idx + 1]  : 0.f;
    float u = (hh > 0)     ? h_in[idx - Ww] : 0.f;
    float d = (hh < Hh-1)  ? h_in[idx + Ww] : 0.f;

    const float* gp = g_g + (size_t)plane * 4 * HW + (hh * Ww + w);
    float g0 = gp[0 * HW], g1 = gp[1 * HW], g2 = gp[2 * HW], g3 = gp[3 * HW];
    float selfw = 1.f - (g0 + g1 + g2 + g3);

    float agg = g0 * l;
    agg += g1 * r;
    agg += g2 * u;
    agg += g3 * d;
    h_out[idx] = selfw * h + agg;
}

// ---------------------------------------------------------------------------
// kernel_launch
// inputs: 0 feats, 1 logits, 2 w1, 3 gamma, 4 beta, 5 mean, 6 var, 7 w2, 8 b2
// ---------------------------------------------------------------------------
extern "C" void kernel_launch(void* const* d_in, const int* in_sizes, int n_in,
                              void* d_out, int out_size)
{
    const float* feats  = (const float*)d_in[0];
    const float* logits = (const float*)d_in[1];
    const float* w1     = (const float*)d_in[2];
    const float* gamma  = (const float*)d_in[3];
    const float* beta   = (const float*)d_in[4];
    const float* mean   = (const float*)d_in[5];
    const float* var    = (const float*)d_in[6];
    const float* w2     = (const float*)d_in[7];
    const float* b2     = (const float*)d_in[8];
    float* out = (float*)d_out;

    float* hbuf;
    cudaGetSymbolAddress((void**)&hbuf, g_h);

    cudaFuncSetAttribute(conv3x3_mma_kernel,
                         cudaFuncAttributeMaxDynamicSharedMemorySize, CSMEM);

    transpose_pad_kernel<<<dim3(HP, B_), dim3(32, 8)>>>(feats);
    prep_w1t_kernel<<<(72 * MID * 32 + 255) / 256, 256>>>(w1);
    conv3x3_mma_kernel<<<dim3(Hh, B_), 256, CSMEM>>>(gamma, beta, mean, var);
    conv1x1_softmax_kernel<<<dim3(HW / 32, B_), 256>>>(w2, b2);
    {
        int total = B_ * Kk * HW;
        int blocks = (total + 255) / 256;
        prop_step_kernel<<<blocks, 256>>>(logits, hbuf);
        prop_step_kernel<<<blocks, 256>>>(hbuf, out);
        prop_step_kernel<<<blocks, 256>>>(out, hbuf);
        prop_step_kernel<<<blocks, 256>>>(hbuf, out);
    }
}

// round 4
// speedup vs baseline: 7.1986x; 1.8200x over previous
#include <cuda_runtime.h>
#include <cuda_fp16.h>
#include <math.h>

// ---------------------------------------------------------------------------
// Problem constants
// ---------------------------------------------------------------------------
#define B_    8
#define CIN   256
#define MID   128
#define Hh    128
#define Ww    256
#define Kk    19
#define HW    (Hh*Ww)          // 32768
#define EPSBN 1e-5f
#define HP    (Hh+2)           // 130
#define WP    (Ww+2)           // 258

// ---------------------------------------------------------------------------
// Scratch (device globals: allocation-free)
// ---------------------------------------------------------------------------
__device__ __half g_ft[(size_t)B_ * HP * WP * CIN];  // fp16 NHWC padded (~137MB)
__device__ __half g_w1h[9 * MID * CIN];              // fp16 [dy][cc][dx][mid][64]
__device__ __half g_w2h[80 * MID];                   // fp16 w2 padded to 80 rows
__device__ __half g_xh[(size_t)B_ * HW * MID];       // fp16 x [b][pixel][mid]
__device__ float  g_g[(size_t)B_ * Kk * HW * 4];     // guidance [b][k][hw][4]
__device__ float  g_h[(size_t)B_ * Kk * HW];         // ping-pong h buffer

// ---------------------------------------------------------------------------
// Helpers
// ---------------------------------------------------------------------------
static __device__ __forceinline__ unsigned smem_u32(const void* p) {
    unsigned r;
    asm("{ .reg .u64 t; cvta.to.shared.u64 t, %1; cvt.u32.u64 %0, t; }"
        : "=r"(r) : "l"(p));
    return r;
}

static __device__ __forceinline__ void cp16(unsigned saddr, const void* gptr) {
    asm volatile("cp.async.cg.shared.global [%0], [%1], 16;"
                 :: "r"(saddr), "l"(gptr));
}

static __device__ __forceinline__ void ldsm4(unsigned* r, unsigned addr) {
    asm volatile("ldmatrix.sync.aligned.m8n8.x4.shared.b16 {%0,%1,%2,%3}, [%4];"
        : "=r"(r[0]), "=r"(r[1]), "=r"(r[2]), "=r"(r[3]) : "r"(addr));
}

static __device__ __forceinline__ void mma16816(float* c, const unsigned* a,
                                                const unsigned* b) {
    asm volatile(
        "mma.sync.aligned.m16n8k16.row.col.f32.f16.f16.f32 "
        "{%0,%1,%2,%3}, {%4,%5,%6,%7}, {%8,%9}, {%0,%1,%2,%3};"
        : "+f"(c[0]), "+f"(c[1]), "+f"(c[2]), "+f"(c[3])
        : "r"(a[0]), "r"(a[1]), "r"(a[2]), "r"(a[3]), "r"(b[0]), "r"(b[1]));
}

// ---------------------------------------------------------------------------
// Kernel T1: feats NCHW -> padded NHWC fp16. grid (HP, B), block (32,8)
// ---------------------------------------------------------------------------
__global__ __launch_bounds__(256) void transpose_pad_kernel(
    const float* __restrict__ feats)
{
    __shared__ float t[32][33];
    const int tx = threadIdx.x, ty = threadIdx.y;
    const int tid = ty * 32 + tx;
    const int hp = blockIdx.x, b = blockIdx.y;
    __half* orow = g_ft + ((size_t)(b * HP + hp) * WP) * CIN;

    if (hp == 0 || hp == HP - 1) {
        for (int idx = tid; idx < WP * CIN; idx += 256)
            orow[idx] = __float2half(0.f);
        return;
    }
    if (tid < 256) {
        orow[tid] = __float2half(0.f);
        orow[(WP - 1) * CIN + tid] = __float2half(0.f);
    }

    const int h = hp - 1;
    for (int wt = 0; wt < 8; wt++) {
        for (int ct = 0; ct < 8; ct++) {
            const int w0 = wt * 32, c0 = ct * 32;
            __syncthreads();
#pragma unroll
            for (int j = 0; j < 4; j++) {
                int ci = c0 + ty + j * 8;
                t[ty + j * 8][tx] =
                    feats[(((size_t)b * CIN + ci) * Hh + h) * Ww + w0 + tx];
            }
            __syncthreads();
#pragma unroll
            for (int j = 0; j < 4; j++) {
                int w = w0 + ty + j * 8;
                orow[(size_t)(w + 1) * CIN + c0 + tx] =
                    __float2half_rn(t[tx][ty + j * 8]);
            }
        }
    }
}

// ---------------------------------------------------------------------------
// Kernel T2: w1 -> fp16 g_w1h[(((dy*4+cc)*3+dx)*128 + mid)*64 + cw]
// ---------------------------------------------------------------------------
__global__ __launch_bounds__(256) void prep_w1h_kernel(const float* __restrict__ w1)
{
    int idx = blockIdx.x * 256 + threadIdx.x;
    if (idx >= 9 * MID * CIN) return;
    int cw = idx & 63;
    int m  = (idx >> 6) & 127;
    int rest = idx >> 13;           // (dy*4+cc)*3 + dx
    int dx = rest % 3, q = rest / 3;
    int cc = q & 3, dy = q >> 2;
    int ci = cc * 64 + cw;
    g_w1h[idx] = __float2half_rn(w1[(((size_t)m * CIN + ci) * 3 + dy) * 3 + dx]);
}

// Kernel T3: w2 -> fp16, padded to 80 output rows
__global__ __launch_bounds__(256) void prep_w2h_kernel(const float* __restrict__ w2)
{
    int idx = blockIdx.x * 256 + threadIdx.x;
    if (idx >= 80 * MID) return;
    int n = idx >> 7, m = idx & 127;
    float v = (n < 76) ? w2[n * MID + m] : 0.f;
    g_w2h[idx] = __float2half_rn(v);
}

// ---------------------------------------------------------------------------
// Kernel G: conv3x3 as fp16 mma.sync implicit GEMM + BN + ReLU epilogue.
// Per CTA one (b,h) row: M=256 px, N=128 mid, K=2304.
// Super-stage t=(dy, cc64), 12 total; A loaded once per t, 3 dx = row shifts.
// A stage: 258 rows x 64 fp16 (128B). B stage: 3 dx x 128 mid x 64 fp16.
// ---------------------------------------------------------------------------
#define A_ST   33024                 // 258*128
#define B_ST   49152                 // 3*128*128
#define STG    (A_ST + B_ST)         // 82176
#define CSMEM  (2 * STG)             // 164352

__global__ void __launch_bounds__(256) conv3x3_mma_kernel(
    const float* __restrict__ gamma, const float* __restrict__ beta,
    const float* __restrict__ mean,  const float* __restrict__ var)
{
    extern __shared__ __align__(1024) unsigned char smem_raw[];
    const unsigned sbase = smem_u32(smem_raw);
    const int tid = threadIdx.x;
    const int L = tid & 31, wid = tid >> 5;
    const int h = blockIdx.x, b = blockIdx.y;
    const int p0w = (wid >> 1) * 64;     // warp m-offset (pixels)
    const int n0w = (wid & 1) * 64;      // warp n-offset (mid)

    auto issue_loads = [&](int t, int buf) {
        const int dy = t >> 2, cc = t & 3;
        const unsigned Ab = sbase + buf * STG;
        const unsigned Bb = Ab + A_ST;
        const __half* asrc = g_ft + ((size_t)(b * HP + h + dy) * WP) * CIN + cc * 64;
#pragma unroll
        for (int i = 0; i < 9; i++) {            // A: 258 rows x 8 chunks = 2064
            int g = tid + i * 256;
            if (g < 2064) {
                int row = g >> 3, c = g & 7;
                cp16(Ab + row * 128 + ((c ^ (row & 7)) << 4),
                     asrc + (size_t)row * CIN + c * 8);
            }
        }
        const __half* bsrc = g_w1h + (size_t)((dy * 4 + cc) * 3) * MID * 64;
#pragma unroll
        for (int i = 0; i < 12; i++) {           // B: 3 x 128 rows x 8 chunks
            int g = tid + i * 256;
            int dxi = g >> 10, row = (g >> 3) & 127, c = g & 7;
            cp16(Bb + dxi * 16384 + row * 128 + ((c ^ (row & 7)) << 4),
                 bsrc + (size_t)dxi * MID * 64 + row * 64 + c * 8);
        }
        asm volatile("cp.async.commit_group;");
    };

    float acc[4][8][4];
#pragma unroll
    for (int mi = 0; mi < 4; mi++)
#pragma unroll
        for (int ni = 0; ni < 8; ni++)
#pragma unroll
            for (int q = 0; q < 4; q++) acc[mi][ni][q] = 0.f;

    issue_loads(0, 0);

    for (int t = 0; t < 12; t++) {
        const int buf = t & 1;
        asm volatile("cp.async.wait_group 0;");
        __syncthreads();
        if (t < 11) issue_loads(t + 1, buf ^ 1);

        const unsigned Ab = sbase + buf * STG;
        const unsigned Bb = Ab + A_ST;
#pragma unroll
        for (int dx = 0; dx < 3; dx++) {
#pragma unroll
            for (int kk = 0; kk < 4; kk++) {     // 4 x k16 over k-depth 64
                unsigned a[4][4], bf[4][4];
#pragma unroll
                for (int mi = 0; mi < 4; mi++) {
                    int row = p0w + mi * 16 + (L & 15) + dx;
                    int ch = 2 * kk + (L >> 4);
                    ldsm4(a[mi], Ab + row * 128 + ((ch ^ (row & 7)) << 4));
                }
#pragma unroll
                for (int jj = 0; jj < 4; jj++) {
                    int row = n0w + jj * 16 + ((L >> 4) << 3) + (L & 7);
                    int ch = 2 * kk + ((L >> 3) & 1);
                    ldsm4(bf[jj], Bb + dx * 16384 + row * 128 +
                                  ((ch ^ (row & 7)) << 4));
                }
#pragma unroll
                for (int mi = 0; mi < 4; mi++)
#pragma unroll
                    for (int ni = 0; ni < 8; ni++)
                        mma16816(acc[mi][ni], a[mi], &bf[ni >> 1][(ni & 1) << 1]);
            }
        }
        __syncthreads();
    }

    // Epilogue: BN + ReLU -> g_xh[b][pixel][mid] fp16
    const int midb = n0w + ((L & 3) << 1);
    float iv0[8], iv1[8], bb0[8], bb1[8];
#pragma unroll
    for (int ni = 0; ni < 8; ni++) {
        int m0 = midb + ni * 8;
        iv0[ni] = gamma[m0]     * rsqrtf(var[m0]     + EPSBN);
        iv1[ni] = gamma[m0 + 1] * rsqrtf(var[m0 + 1] + EPSBN);
        bb0[ni] = beta[m0]     - mean[m0]     * iv0[ni];
        bb1[ni] = beta[m0 + 1] - mean[m0 + 1] * iv1[ni];
    }
#pragma unroll
    for (int mi = 0; mi < 4; mi++) {
        int p0 = p0w + mi * 16 + (L >> 2);
        __half* o = g_xh + ((size_t)b * HW + (size_t)h * Ww + p0) * MID;
#pragma unroll
        for (int ni = 0; ni < 8; ni++) {
            int m0 = midb + ni * 8;
            float u0 = fmaxf(fmaf(acc[mi][ni][0], iv0[ni], bb0[ni]), 0.f);
            float u1 = fmaxf(fmaf(acc[mi][ni][1], iv1[ni], bb1[ni]), 0.f);
            float u2 = fmaxf(fmaf(acc[mi][ni][2], iv0[ni], bb0[ni]), 0.f);
            float u3 = fmaxf(fmaf(acc[mi][ni][3], iv1[ni], bb1[ni]), 0.f);
            *(__half2*)(o + m0)           = __floats2half2_rn(u0, u1);
            *(__half2*)(o + 8 * MID + m0) = __floats2half2_rn(u2, u3);
        }
    }
}

// ---------------------------------------------------------------------------
// Kernel 2: conv1x1 as fp16 mma GEMM + bias + softmax over 4 dirs.
// Per CTA: 256 px (M) x 80 n (K*4 padded) x K=128. 8 warps, warp = 32 px x 80 n.
// Output g in [b][k][hw][4] layout.
// ---------------------------------------------------------------------------
#define C1_A   65536                 // 256 rows x 256B
#define C1_B   20480                 // 80 rows x 256B
#define C1SMEM (C1_A + C1_B)

static __device__ __forceinline__ unsigned swz256(int row, int ch) {
    return row * 256 + ((ch & 8) << 4) + (((ch & 7) ^ (row & 7)) << 4);
}

__global__ void __launch_bounds__(256) conv1x1_mma_softmax_kernel(
    const float* __restrict__ b2)
{
    extern __shared__ __align__(1024) unsigned char smem_raw[];
    const unsigned sA = smem_u32(smem_raw);
    const unsigned sB = sA + C1_A;
    const int tid = threadIdx.x;
    const int L = tid & 31, wid = tid >> 5;
    const int p0 = blockIdx.x * 256, b = blockIdx.y;

    const __half* xsrc = g_xh + ((size_t)b * HW + p0) * MID;
#pragma unroll
    for (int i = 0; i < 16; i++) {               // A: 256 rows x 16 chunks
        int g = tid + i * 256;
        int row = g >> 4, c = g & 15;
        cp16(sA + swz256(row, c), xsrc + (size_t)row * MID + c * 8);
    }
#pragma unroll
    for (int i = 0; i < 5; i++) {                // B: 80 rows x 16 chunks
        int g = tid + i * 256;
        int row = g >> 4, c = g & 15;
        cp16(sB + swz256(row, c), g_w2h + (size_t)row * MID + c * 8);
    }
    asm volatile("cp.async.commit_group;");
    asm volatile("cp.async.wait_group 0;");
    __syncthreads();

    const int pw = wid * 32;
    float acc[2][10][4];
#pragma unroll
    for (int mi = 0; mi < 2; mi++)
#pragma unroll
        for (int ni = 0; ni < 10; ni++)
#pragma unroll
            for (int q = 0; q < 4; q++) acc[mi][ni][q] = 0.f;

#pragma unroll
    for (int kk = 0; kk < 8; kk++) {
        unsigned a[2][4], bf[5][4];
#pragma unroll
        for (int mi = 0; mi < 2; mi++) {
            int row = pw + mi * 16 + (L & 15);
            int ch = 2 * kk + (L >> 4);
            ldsm4(a[mi], sA + swz256(row, ch));
        }
#pragma unroll
        for (int jj = 0; jj < 5; jj++) {
            int row = jj * 16 + ((L >> 4) << 3) + (L & 7);
            int ch = 2 * kk + ((L >> 3) & 1);
            ldsm4(bf[jj], sB + swz256(row, ch));
        }
#pragma unroll
        for (int mi = 0; mi < 2; mi++)
#pragma unroll
            for (int ni = 0; ni < 10; ni++)
                mma16816(acc[mi][ni], a[mi], &bf[ni >> 1][(ni & 1) << 1]);
    }

    // Softmax epilogue. Thread holds n = 8*ni + 2*(L&3) + {0,1}.
    // Lane pair (L, L^1) holds the 4 dirs of one k.
    const int d0 = (L & 1) * 2;                  // my dirs: {d0, d0+1}
#pragma unroll
    for (int mi = 0; mi < 2; mi++) {
#pragma unroll
        for (int h2 = 0; h2 < 2; h2++) {
            int px = p0 + pw + mi * 16 + (L >> 2) + h2 * 8;
#pragma unroll
            for (int ni = 0; ni < 10; ni++) {
                int n0 = 8 * ni + 2 * (L & 3);
                bool valid = (n0 < 76);
                float bb0 = valid ? b2[n0] : 0.f;
                float bb1 = valid ? b2[n0 + 1] : 0.f;
                float v0 = acc[mi][ni][2 * h2]     + bb0;
                float v1 = acc[mi][ni][2 * h2 + 1] + bb1;
                float p0v = __shfl_xor_sync(0xFFFFFFFFu, v0, 1);
                float p1v = __shfl_xor_sync(0xFFFFFFFFu, v1, 1);
                float mx = fmaxf(fmaxf(v0, v1), fmaxf(p0v, p1v));
                float e0 = expf(v0 - mx), e1 = expf(v1 - mx);
                float ep0 = expf(p0v - mx), ep1 = expf(p1v - mx);
                float inv = 1.f / (e0 + e1 + ep0 + ep1);
                if (valid) {
                    int k = n0 >> 2;
                    float2 r; r.x = e0 * inv; r.y = e1 * inv;
                    *(float2*)(g_g + (((size_t)b * Kk + k) * HW + px) * 4 + d0) = r;
                }
            }
        }
    }
}

// ---------------------------------------------------------------------------
// Kernel 3: one propagation step; g layout [b][k][hw][4] -> float4 loads
// ---------------------------------------------------------------------------
__global__ __launch_bounds__(256) void prop_step_kernel(
    const float* __restrict__ h_in, float* __restrict__ h_out)
{
    int idx = blockIdx.x * 256 + threadIdx.x;
    const int total = B_ * Kk * HW;
    if (idx >= total) return;

    int w  = idx & (Ww - 1);
    int hh = (idx >> 8) & (Hh - 1);

    float h = h_in[idx];
    float l = (w > 0)      ? h_in[idx - 1]  : 0.f;
    float r = (w < Ww - 1) ? h_in[idx + 1]  : 0.f;
    float u = (hh > 0)     ? h_in[idx - Ww] : 0.f;
    float d = (hh < Hh-1)  ? h_in[idx + Ww] : 0.f;

    float4 gv = *(const float4*)(g_g + (size_t)idx * 4);
    float selfw = 1.f - (gv.x + gv.y + gv.z + gv.w);

    float agg = gv.x * l;
    agg += gv.y * r;
    agg += gv.z * u;
    agg += gv.w * d;
    h_out[idx] = selfw * h + agg;
}

// ---------------------------------------------------------------------------
// kernel_launch
// inputs: 0 feats, 1 logits, 2 w1, 3 gamma, 4 beta, 5 mean, 6 var, 7 w2, 8 b2
// ---------------------------------------------------------------------------
extern "C" void kernel_launch(void* const* d_in, const int* in_sizes, int n_in,
                              void* d_out, int out_size)
{
    const float* feats  = (const float*)d_in[0];
    const float* logits = (const float*)d_in[1];
    const float* w1     = (const float*)d_in[2];
    const float* gamma  = (const float*)d_in[3];
    const float* beta   = (const float*)d_in[4];
    const float* mean   = (const float*)d_in[5];
    const float* var    = (const float*)d_in[6];
    const float* w2     = (const float*)d_in[7];
    const float* b2     = (const float*)d_in[8];
    float* out = (float*)d_out;

    float* hbuf;
    cudaGetSymbolAddress((void**)&hbuf, g_h);

    cudaFuncSetAttribute(conv3x3_mma_kernel,
                         cudaFuncAttributeMaxDynamicSharedMemorySize, CSMEM);
    cudaFuncSetAttribute(conv1x1_mma_softmax_kernel,
                         cudaFuncAttributeMaxDynamicSharedMemorySize, C1SMEM);

    transpose_pad_kernel<<<dim3(HP, B_), dim3(32, 8)>>>(feats);
    prep_w1h_kernel<<<(9 * MID * CIN + 255) / 256, 256>>>(w1);
    prep_w2h_kernel<<<(80 * MID + 255) / 256, 256>>>(w2);
    conv3x3_mma_kernel<<<dim3(Hh, B_), 256, CSMEM>>>(gamma, beta, mean, var);
    conv1x1_mma_softmax_kernel<<<dim3(HW / 256, B_), 256, C1SMEM>>>(b2);
    {
        int total = B_ * Kk * HW;
        int blocks = (total + 255) / 256;
        prop_step_kernel<<<blocks, 256>>>(logits, hbuf);
        prop_step_kernel<<<blocks, 256>>>(hbuf, out);
        prop_step_kernel<<<blocks, 256>>>(out, hbuf);
        prop_step_kernel<<<blocks, 256>>>(hbuf, out);
    }
}

// round 5
// speedup vs baseline: 7.5129x; 1.0437x over previous
#include <cuda_runtime.h>
#include <cuda_fp16.h>
#include <math.h>

// ---------------------------------------------------------------------------
// Problem constants
// ---------------------------------------------------------------------------
#define B_    8
#define CIN   256
#define MID   128
#define Hh    128
#define Ww    256
#define Kk    19
#define HW    (Hh*Ww)          // 32768
#define EPSBN 1e-5f
#define HP    (Hh+2)           // 130
#define WP    (Ww+2)           // 258

// ---------------------------------------------------------------------------
// Scratch (device globals: allocation-free)
// ---------------------------------------------------------------------------
__device__ __half g_ft[(size_t)B_ * HP * WP * CIN];  // fp16 NHWC padded
__device__ __half g_w1h[9 * MID * CIN];              // fp16 [(dy*8+cc)*3+dx][mid][32]
__device__ __half g_w2h[80 * MID];                   // fp16 w2 padded to 80 rows
__device__ __half g_xh[(size_t)B_ * HW * MID];       // fp16 x [b][pixel][mid]
__device__ float  g_g[(size_t)B_ * Kk * HW * 4];     // guidance [b][k][hw][4]

// ---------------------------------------------------------------------------
// Helpers
// ---------------------------------------------------------------------------
static __device__ __forceinline__ unsigned smem_u32(const void* p) {
    unsigned r;
    asm("{ .reg .u64 t; cvta.to.shared.u64 t, %1; cvt.u32.u64 %0, t; }"
        : "=r"(r) : "l"(p));
    return r;
}

static __device__ __forceinline__ void cp16(unsigned saddr, const void* gptr) {
    asm volatile("cp.async.cg.shared.global [%0], [%1], 16;"
                 :: "r"(saddr), "l"(gptr));
}

static __device__ __forceinline__ void ldsm4(unsigned* r, unsigned addr) {
    asm volatile("ldmatrix.sync.aligned.m8n8.x4.shared.b16 {%0,%1,%2,%3}, [%4];"
        : "=r"(r[0]), "=r"(r[1]), "=r"(r[2]), "=r"(r[3]) : "r"(addr));
}

static __device__ __forceinline__ void mma16816(float* c, const unsigned* a,
                                                const unsigned* b) {
    asm volatile(
        "mma.sync.aligned.m16n8k16.row.col.f32.f16.f16.f32 "
        "{%0,%1,%2,%3}, {%4,%5,%6,%7}, {%8,%9}, {%0,%1,%2,%3};"
        : "+f"(c[0]), "+f"(c[1]), "+f"(c[2]), "+f"(c[3])
        : "r"(a[0]), "r"(a[1]), "r"(a[2]), "r"(a[3]), "r"(b[0]), "r"(b[1]));
}

// swizzled offset within a 64B-row tile: 4 chunks of 16B per row
static __device__ __forceinline__ unsigned swz64(int row, int ch) {
    return row * 64 + ((ch ^ ((row >> 1) & 3)) << 4);
}

// ---------------------------------------------------------------------------
// Kernel T1: feats NCHW -> padded NHWC fp16. grid (HP, B), block (32,8)
// ---------------------------------------------------------------------------
__global__ __launch_bounds__(256) void transpose_pad_kernel(
    const float* __restrict__ feats)
{
    __shared__ float t[32][33];
    const int tx = threadIdx.x, ty = threadIdx.y;
    const int tid = ty * 32 + tx;
    const int hp = blockIdx.x, b = blockIdx.y;
    __half* orow = g_ft + ((size_t)(b * HP + hp) * WP) * CIN;

    if (hp == 0 || hp == HP - 1) {
        for (int idx = tid; idx < WP * CIN; idx += 256)
            orow[idx] = __float2half(0.f);
        return;
    }
    if (tid < 256) {
        orow[tid] = __float2half(0.f);
        orow[(WP - 1) * CIN + tid] = __float2half(0.f);
    }

    const int h = hp - 1;
    for (int wt = 0; wt < 8; wt++) {
        for (int ct = 0; ct < 8; ct++) {
            const int w0 = wt * 32, c0 = ct * 32;
            __syncthreads();
#pragma unroll
            for (int j = 0; j < 4; j++) {
                int ci = c0 + ty + j * 8;
                t[ty + j * 8][tx] =
                    feats[(((size_t)b * CIN + ci) * Hh + h) * Ww + w0 + tx];
            }
            __syncthreads();
#pragma unroll
            for (int j = 0; j < 4; j++) {
                int w = w0 + ty + j * 8;
                orow[(size_t)(w + 1) * CIN + c0 + tx] =
                    __float2half_rn(t[tx][ty + j * 8]);
            }
        }
    }
}

// ---------------------------------------------------------------------------
// Kernel T2: w1 -> fp16 g_w1h[(((dy*8+cc)*3+dx)*128 + mid)*32 + cw]
// ---------------------------------------------------------------------------
__global__ __launch_bounds__(256) void prep_w1h_kernel(const float* __restrict__ w1)
{
    int idx = blockIdx.x * 256 + threadIdx.x;
    if (idx >= 9 * MID * CIN) return;
    int cw = idx & 31;
    int m  = (idx >> 5) & 127;
    int rest = idx >> 12;           // (dy*8+cc)*3 + dx
    int dx = rest % 3, q = rest / 3;
    int cc = q & 7, dy = q >> 3;
    int ci = cc * 32 + cw;
    g_w1h[idx] = __float2half_rn(w1[(((size_t)m * CIN + ci) * 3 + dy) * 3 + dx]);
}

// Kernel T3: w2 -> fp16, padded to 80 output rows
__global__ __launch_bounds__(256) void prep_w2h_kernel(const float* __restrict__ w2)
{
    int idx = blockIdx.x * 256 + threadIdx.x;
    if (idx >= 80 * MID) return;
    int n = idx >> 7, m = idx & 127;
    float v = (n < 76) ? w2[n * MID + m] : 0.f;
    g_w2h[idx] = __float2half_rn(v);
}

// ---------------------------------------------------------------------------
// Kernel G: conv3x3 fp16 mma implicit GEMM, 4-deep cp.async pipeline.
// Per CTA one (b,h) row: M=256 px, N=128 mid, K=2304.
// Stage t=(dy,cc32), 24 stages. A: 258 rows x 32 fp16 (64B). B: 3dx x 128 x 32.
// ---------------------------------------------------------------------------
#define A_ST   16512                 // 258*64
#define B_ST   24576                 // 3*128*64
#define STG    (A_ST + B_ST)         // 41088
#define NSTG   4
#define CSMEM  (NSTG * STG)          // 164352

__global__ void __launch_bounds__(256) conv3x3_mma_kernel(
    const float* __restrict__ gamma, const float* __restrict__ beta,
    const float* __restrict__ mean,  const float* __restrict__ var)
{
    extern __shared__ __align__(1024) unsigned char smem_raw[];
    const unsigned sbase = smem_u32(smem_raw);
    const int tid = threadIdx.x;
    const int L = tid & 31, wid = tid >> 5;
    const int h = blockIdx.x, b = blockIdx.y;
    const int p0w = (wid >> 1) * 64;     // warp m-offset (pixels)
    const int n0w = (wid & 1) * 64;      // warp n-offset (mid)

    auto issue_loads = [&](int t, int buf) {
        const int dy = t >> 3, cc = t & 7;
        const unsigned Ab = sbase + buf * STG;
        const unsigned Bb = Ab + A_ST;
        const __half* asrc = g_ft + ((size_t)(b * HP + h + dy) * WP) * CIN + cc * 32;
#pragma unroll
        for (int i = 0; i < 5; i++) {            // A: 258 rows x 4 chunks = 1032
            int g = tid + i * 256;
            if (g < 1032) {
                int row = g >> 2, c = g & 3;
                cp16(Ab + swz64(row, c), asrc + (size_t)row * CIN + c * 8);
            }
        }
        const __half* bsrc = g_w1h + (size_t)((dy * 8 + cc) * 3) * MID * 32;
#pragma unroll
        for (int i = 0; i < 6; i++) {            // B: 3 x 128 rows x 4 chunks
            int g = tid + i * 256;
            int dxi = g >> 9, row = (g >> 2) & 127, c = g & 3;
            cp16(Bb + dxi * 8192 + swz64(row, c),
                 bsrc + (size_t)dxi * MID * 32 + row * 32 + c * 8);
        }
        asm volatile("cp.async.commit_group;");
    };

    float acc[4][8][4];
#pragma unroll
    for (int mi = 0; mi < 4; mi++)
#pragma unroll
        for (int ni = 0; ni < 8; ni++)
#pragma unroll
            for (int q = 0; q < 4; q++) acc[mi][ni][q] = 0.f;

    issue_loads(0, 0);
    issue_loads(1, 1);
    issue_loads(2, 2);

    for (int t = 0; t < 24; t++) {
        const int buf = t & (NSTG - 1);
        if (t < 22)      asm volatile("cp.async.wait_group 2;");
        else if (t == 22) asm volatile("cp.async.wait_group 1;");
        else              asm volatile("cp.async.wait_group 0;");
        __syncthreads();
        if (t < 21) issue_loads(t + 3, (t + 3) & (NSTG - 1));

        const unsigned Ab = sbase + buf * STG;
        const unsigned Bb = Ab + A_ST;
#pragma unroll
        for (int dx = 0; dx < 3; dx++) {
#pragma unroll
            for (int kk = 0; kk < 2; kk++) {     // 2 x k16 over k-depth 32
                unsigned a[4][4], bf[4][4];
#pragma unroll
                for (int mi = 0; mi < 4; mi++) {
                    int row = p0w + mi * 16 + (L & 15) + dx;
                    ldsm4(a[mi], Ab + swz64(row, 2 * kk + (L >> 4)));
                }
#pragma unroll
                for (int jj = 0; jj < 4; jj++) {
                    int row = n0w + jj * 16 + ((L >> 4) << 3) + (L & 7);
                    ldsm4(bf[jj], Bb + dx * 8192 +
                                  swz64(row, 2 * kk + ((L >> 3) & 1)));
                }
#pragma unroll
                for (int mi = 0; mi < 4; mi++)
#pragma unroll
                    for (int ni = 0; ni < 8; ni++)
                        mma16816(acc[mi][ni], a[mi], &bf[ni >> 1][(ni & 1) << 1]);
            }
        }
    }

    // Epilogue: BN + ReLU -> g_xh[b][pixel][mid] fp16
    const int midb = n0w + ((L & 3) << 1);
    float iv0[8], iv1[8], bb0[8], bb1[8];
#pragma unroll
    for (int ni = 0; ni < 8; ni++) {
        int m0 = midb + ni * 8;
        iv0[ni] = gamma[m0]     * rsqrtf(var[m0]     + EPSBN);
        iv1[ni] = gamma[m0 + 1] * rsqrtf(var[m0 + 1] + EPSBN);
        bb0[ni] = beta[m0]     - mean[m0]     * iv0[ni];
        bb1[ni] = beta[m0 + 1] - mean[m0 + 1] * iv1[ni];
    }
#pragma unroll
    for (int mi = 0; mi < 4; mi++) {
        int p0 = p0w + mi * 16 + (L >> 2);
        __half* o = g_xh + ((size_t)b * HW + (size_t)h * Ww + p0) * MID;
#pragma unroll
        for (int ni = 0; ni < 8; ni++) {
            int m0 = midb + ni * 8;
            float u0 = fmaxf(fmaf(acc[mi][ni][0], iv0[ni], bb0[ni]), 0.f);
            float u1 = fmaxf(fmaf(acc[mi][ni][1], iv1[ni], bb1[ni]), 0.f);
            float u2 = fmaxf(fmaf(acc[mi][ni][2], iv0[ni], bb0[ni]), 0.f);
            float u3 = fmaxf(fmaf(acc[mi][ni][3], iv1[ni], bb1[ni]), 0.f);
            *(__half2*)(o + m0)           = __floats2half2_rn(u0, u1);
            *(__half2*)(o + 8 * MID + m0) = __floats2half2_rn(u2, u3);
        }
    }
}

// ---------------------------------------------------------------------------
// Kernel 2: conv1x1 as fp16 mma GEMM + bias + softmax over 4 dirs.
// ---------------------------------------------------------------------------
#define C1_A   65536                 // 256 rows x 256B
#define C1_B   20480                 // 80 rows x 256B
#define C1SMEM (C1_A + C1_B)

static __device__ __forceinline__ unsigned swz256(int row, int ch) {
    return row * 256 + ((ch & 8) << 4) + (((ch & 7) ^ (row & 7)) << 4);
}

__global__ void __launch_bounds__(256) conv1x1_mma_softmax_kernel(
    const float* __restrict__ b2)
{
    extern __shared__ __align__(1024) unsigned char smem_raw[];
    const unsigned sA = smem_u32(smem_raw);
    const unsigned sB = sA + C1_A;
    const int tid = threadIdx.x;
    const int L = tid & 31, wid = tid >> 5;
    const int p0 = blockIdx.x * 256, b = blockIdx.y;

    const __half* xsrc = g_xh + ((size_t)b * HW + p0) * MID;
#pragma unroll
    for (int i = 0; i < 16; i++) {               // A: 256 rows x 16 chunks
        int g = tid + i * 256;
        int row = g >> 4, c = g & 15;
        cp16(sA + swz256(row, c), xsrc + (size_t)row * MID + c * 8);
    }
#pragma unroll
    for (int i = 0; i < 5; i++) {                // B: 80 rows x 16 chunks
        int g = tid + i * 256;
        int row = g >> 4, c = g & 15;
        cp16(sB + swz256(row, c), g_w2h + (size_t)row * MID + c * 8);
    }
    asm volatile("cp.async.commit_group;");
    asm volatile("cp.async.wait_group 0;");
    __syncthreads();

    const int pw = wid * 32;
    float acc[2][10][4];
#pragma unroll
    for (int mi = 0; mi < 2; mi++)
#pragma unroll
        for (int ni = 0; ni < 10; ni++)
#pragma unroll
            for (int q = 0; q < 4; q++) acc[mi][ni][q] = 0.f;

#pragma unroll
    for (int kk = 0; kk < 8; kk++) {
        unsigned a[2][4], bf[5][4];
#pragma unroll
        for (int mi = 0; mi < 2; mi++) {
            int row = pw + mi * 16 + (L & 15);
            ldsm4(a[mi], sA + swz256(row, 2 * kk + (L >> 4)));
        }
#pragma unroll
        for (int jj = 0; jj < 5; jj++) {
            int row = jj * 16 + ((L >> 4) << 3) + (L & 7);
            ldsm4(bf[jj], sB + swz256(row, 2 * kk + ((L >> 3) & 1)));
        }
#pragma unroll
        for (int mi = 0; mi < 2; mi++)
#pragma unroll
            for (int ni = 0; ni < 10; ni++)
                mma16816(acc[mi][ni], a[mi], &bf[ni >> 1][(ni & 1) << 1]);
    }

    const int d0 = (L & 1) * 2;
#pragma unroll
    for (int mi = 0; mi < 2; mi++) {
#pragma unroll
        for (int h2 = 0; h2 < 2; h2++) {
            int px = p0 + pw + mi * 16 + (L >> 2) + h2 * 8;
#pragma unroll
            for (int ni = 0; ni < 10; ni++) {
                int n0 = 8 * ni + 2 * (L & 3);
                bool valid = (n0 < 76);
                float bb0 = valid ? b2[n0] : 0.f;
                float bb1 = valid ? b2[n0 + 1] : 0.f;
                float v0 = acc[mi][ni][2 * h2]     + bb0;
                float v1 = acc[mi][ni][2 * h2 + 1] + bb1;
                float p0v = __shfl_xor_sync(0xFFFFFFFFu, v0, 1);
                float p1v = __shfl_xor_sync(0xFFFFFFFFu, v1, 1);
                float mx = fmaxf(fmaxf(v0, v1), fmaxf(p0v, p1v));
                float e0 = expf(v0 - mx), e1 = expf(v1 - mx);
                float ep0 = expf(p0v - mx), ep1 = expf(p1v - mx);
                float inv = 1.f / (e0 + e1 + ep0 + ep1);
                if (valid) {
                    int k = n0 >> 2;
                    float2 r; r.x = e0 * inv; r.y = e1 * inv;
                    *(float2*)(g_g + (((size_t)b * Kk + k) * HW + px) * 4 + d0) = r;
                }
            }
        }
    }
}

// ---------------------------------------------------------------------------
// Kernel 3: all 4 propagation steps fused; 32x32 output tile + halo 4.
// grid (8, 4, B*K), block 256. g read ONCE per tile.
// ---------------------------------------------------------------------------
#define TR 40                         // loaded region 40x40

template<int S>
static __device__ __forceinline__ void prop_step_smem(
    const float* __restrict__ src, float* __restrict__ dst,
    const float* __restrict__ sg, int tid)
{
    const int n = TR - 2 * S;
    for (int q = tid; q < n * n; q += 256) {
        int r = S + q / n, c = S + q % n;
        int id = r * TR + c;
        float4 gv = *(const float4*)(sg + id * 4);
        float hc = src[id];
        float l = src[id - 1], rr = src[id + 1];
        float u = src[id - TR], d = src[id + TR];
        float selfw = 1.f - (gv.x + gv.y + gv.z + gv.w);
        dst[id] = selfw * hc + gv.x * l + gv.y * rr + gv.z * u + gv.w * d;
    }
}

__global__ __launch_bounds__(256) void prop_fused_kernel(
    const float* __restrict__ logits, float* __restrict__ h_out)
{
    __shared__ float sg[TR * TR * 4];
    __shared__ float sh[2][TR * TR];

    const int tid = threadIdx.x;
    const int wo = blockIdx.x * 32, ho = blockIdx.y * 32;
    const int plane = blockIdx.z;
    const float* hsrc = logits + (size_t)plane * HW;
    const float* gsrc = g_g + (size_t)plane * HW * 4;

    for (int q = tid; q < TR * TR; q += 256) {
        int r = q / TR, c = q % TR;
        int gr = ho + r - 4, gc = wo + c - 4;
        bool in = ((unsigned)gr < (unsigned)Hh) && ((unsigned)gc < (unsigned)Ww);
        float4 gv = make_float4(0.f, 0.f, 0.f, 0.f);
        float hv = 0.f;
        if (in) {
            gv = *(const float4*)(gsrc + ((size_t)gr * Ww + gc) * 4);
            hv = hsrc[(size_t)gr * Ww + gc];
        }
        *(float4*)(sg + q * 4) = gv;
        sh[0][q] = hv;
    }
    __syncthreads();

    prop_step_smem<1>(sh[0], sh[1], sg, tid);
    __syncthreads();
    prop_step_smem<2>(sh[1], sh[0], sg, tid);
    __syncthreads();
    prop_step_smem<3>(sh[0], sh[1], sg, tid);
    __syncthreads();

    // step 4: compute 32x32 and write straight to gmem
    const float* src = sh[1];
    for (int q = tid; q < 32 * 32; q += 256) {
        int r = 4 + (q >> 5), c = 4 + (q & 31);
        int id = r * TR + c;
        float4 gv = *(const float4*)(sg + id * 4);
        float hc = src[id];
        float l = src[id - 1], rr = src[id + 1];
        float u = src[id - TR], d = src[id + TR];
        float selfw = 1.f - (gv.x + gv.y + gv.z + gv.w);
        float res = selfw * hc + gv.x * l + gv.y * rr + gv.z * u + gv.w * d;
        h_out[(size_t)plane * HW + (size_t)(ho + r - 4) * Ww + (wo + c - 4)] = res;
    }
}

// ---------------------------------------------------------------------------
// kernel_launch
// inputs: 0 feats, 1 logits, 2 w1, 3 gamma, 4 beta, 5 mean, 6 var, 7 w2, 8 b2
// ---------------------------------------------------------------------------
extern "C" void kernel_launch(void* const* d_in, const int* in_sizes, int n_in,
                              void* d_out, int out_size)
{
    const float* feats  = (const float*)d_in[0];
    const float* logits = (const float*)d_in[1];
    const float* w1     = (const float*)d_in[2];
    const float* gamma  = (const float*)d_in[3];
    const float* beta   = (const float*)d_in[4];
    const float* mean   = (const float*)d_in[5];
    const float* var    = (const float*)d_in[6];
    const float* w2     = (const float*)d_in[7];
    const float* b2     = (const float*)d_in[8];
    float* out = (float*)d_out;

    cudaFuncSetAttribute(conv3x3_mma_kernel,
                         cudaFuncAttributeMaxDynamicSharedMemorySize, CSMEM);
    cudaFuncSetAttribute(conv1x1_mma_softmax_kernel,
                         cudaFuncAttributeMaxDynamicSharedMemorySize, C1SMEM);

    transpose_pad_kernel<<<dim3(HP, B_), dim3(32, 8)>>>(feats);
    prep_w1h_kernel<<<(9 * MID * CIN + 255) / 256, 256>>>(w1);
    prep_w2h_kernel<<<(80 * MID + 255) / 256, 256>>>(w2);
    conv3x3_mma_kernel<<<dim3(Hh, B_), 256, CSMEM>>>(gamma, beta, mean, var);
    conv1x1_mma_softmax_kernel<<<dim3(HW / 256, B_), 256, C1SMEM>>>(b2);
    prop_fused_kernel<<<dim3(Ww / 32, Hh / 32, B_ * Kk), 256>>>(logits, out);
}

// round 6
// speedup vs baseline: 7.5684x; 1.0074x over previous
#include <cuda_runtime.h>
#include <cuda_fp16.h>
#include <math.h>

// ---------------------------------------------------------------------------
// Problem constants
// ---------------------------------------------------------------------------
#define B_    8
#define CIN   256
#define MID   128
#define Hh    128
#define Ww    256
#define Kk    19
#define HW    (Hh*Ww)          // 32768
#define EPSBN 1e-5f
#define HP    (Hh+2)           // 130
#define WP    (Ww+2)           // 258

// ---------------------------------------------------------------------------
// Scratch (device globals: allocation-free)
// ---------------------------------------------------------------------------
__device__ __half g_ft[(size_t)B_ * HP * WP * CIN];  // fp16 NHWC padded
__device__ __half g_w1h[9 * MID * CIN];              // fp16 [(dy*8+cc)*3+dx][mid][32]
__device__ __half g_w2h[80 * MID];                   // fp16 w2 padded to 80 rows
__device__ __half g_xh[(size_t)B_ * HW * MID];       // fp16 x [b][pixel][mid]
__device__ float  g_g[(size_t)B_ * Kk * HW * 4];     // guidance [b][k][hw][4]

// ---------------------------------------------------------------------------
// Helpers
// ---------------------------------------------------------------------------
static __device__ __forceinline__ unsigned smem_u32(const void* p) {
    unsigned r;
    asm("{ .reg .u64 t; cvta.to.shared.u64 t, %1; cvt.u32.u64 %0, t; }"
        : "=r"(r) : "l"(p));
    return r;
}

static __device__ __forceinline__ void cp16(unsigned saddr, const void* gptr) {
    asm volatile("cp.async.cg.shared.global [%0], [%1], 16;"
                 :: "r"(saddr), "l"(gptr));
}

static __device__ __forceinline__ void ldsm4(unsigned* r, unsigned addr) {
    asm volatile("ldmatrix.sync.aligned.m8n8.x4.shared.b16 {%0,%1,%2,%3}, [%4];"
        : "=r"(r[0]), "=r"(r[1]), "=r"(r[2]), "=r"(r[3]) : "r"(addr));
}

static __device__ __forceinline__ void mma16816(float* c, const unsigned* a,
                                                const unsigned* b) {
    asm volatile(
        "mma.sync.aligned.m16n8k16.row.col.f32.f16.f16.f32 "
        "{%0,%1,%2,%3}, {%4,%5,%6,%7}, {%8,%9}, {%0,%1,%2,%3};"
        : "+f"(c[0]), "+f"(c[1]), "+f"(c[2]), "+f"(c[3])
        : "r"(a[0]), "r"(a[1]), "r"(a[2]), "r"(a[3]), "r"(b[0]), "r"(b[1]));
}

// swizzled offset within a 64B-row tile: 4 chunks of 16B per row
static __device__ __forceinline__ unsigned swz64(int row, int ch) {
    return row * 64 + ((ch ^ ((row >> 1) & 3)) << 4);
}

// ---------------------------------------------------------------------------
// Kernel T1: feats NCHW -> padded NHWC fp16. grid (HP, B), block (32,8)
// ---------------------------------------------------------------------------
__global__ __launch_bounds__(256) void transpose_pad_kernel(
    const float* __restrict__ feats)
{
    __shared__ float t[32][33];
    const int tx = threadIdx.x, ty = threadIdx.y;
    const int tid = ty * 32 + tx;
    const int hp = blockIdx.x, b = blockIdx.y;
    __half* orow = g_ft + ((size_t)(b * HP + hp) * WP) * CIN;

    if (hp == 0 || hp == HP - 1) {
        for (int idx = tid; idx < WP * CIN; idx += 256)
            orow[idx] = __float2half(0.f);
        return;
    }
    if (tid < 256) {
        orow[tid] = __float2half(0.f);
        orow[(WP - 1) * CIN + tid] = __float2half(0.f);
    }

    const int h = hp - 1;
    for (int wt = 0; wt < 8; wt++) {
        for (int ct = 0; ct < 8; ct++) {
            const int w0 = wt * 32, c0 = ct * 32;
            __syncthreads();
#pragma unroll
            for (int j = 0; j < 4; j++) {
                int ci = c0 + ty + j * 8;
                t[ty + j * 8][tx] =
                    feats[(((size_t)b * CIN + ci) * Hh + h) * Ww + w0 + tx];
            }
            __syncthreads();
#pragma unroll
            for (int j = 0; j < 4; j++) {
                int w = w0 + ty + j * 8;
                orow[(size_t)(w + 1) * CIN + c0 + tx] =
                    __float2half_rn(t[tx][ty + j * 8]);
            }
        }
    }
}

// ---------------------------------------------------------------------------
// Kernel T2: w1 -> fp16 g_w1h[(((dy*8+cc)*3+dx)*128 + mid)*32 + cw]
// ---------------------------------------------------------------------------
__global__ __launch_bounds__(256) void prep_w1h_kernel(const float* __restrict__ w1)
{
    int idx = blockIdx.x * 256 + threadIdx.x;
    if (idx >= 9 * MID * CIN) return;
    int cw = idx & 31;
    int m  = (idx >> 5) & 127;
    int rest = idx >> 12;           // (dy*8+cc)*3 + dx
    int dx = rest % 3, q = rest / 3;
    int cc = q & 7, dy = q >> 3;
    int ci = cc * 32 + cw;
    g_w1h[idx] = __float2half_rn(w1[(((size_t)m * CIN + ci) * 3 + dy) * 3 + dx]);
}

// Kernel T3: w2 -> fp16, padded to 80 output rows
__global__ __launch_bounds__(256) void prep_w2h_kernel(const float* __restrict__ w2)
{
    int idx = blockIdx.x * 256 + threadIdx.x;
    if (idx >= 80 * MID) return;
    int n = idx >> 7, m = idx & 127;
    float v = (n < 76) ? w2[n * MID + m] : 0.f;
    g_w2h[idx] = __float2half_rn(v);
}

// ---------------------------------------------------------------------------
// Kernel G: conv3x3 fp16 mma implicit GEMM, 4-deep cp.async pipeline +
// register-level fragment double buffering (ldsm for group g+1 issued
// before mma of group g).
// Per CTA one (b,h) row: M=256 px, N=128 mid, K=2304.
// Stage t=(dy,cc32), 24 stages. A: 258 rows x 32 fp16 (64B). B: 3dx x 128 x 32.
// ---------------------------------------------------------------------------
#define A_ST   16512                 // 258*64
#define B_ST   24576                 // 3*128*64
#define STG    (A_ST + B_ST)         // 41088
#define NSTG   4
#define CSMEM  (NSTG * STG)          // 164352

__global__ void __launch_bounds__(256) conv3x3_mma_kernel(
    const float* __restrict__ gamma, const float* __restrict__ beta,
    const float* __restrict__ mean,  const float* __restrict__ var)
{
    extern __shared__ __align__(1024) unsigned char smem_raw[];
    const unsigned sbase = smem_u32(smem_raw);
    const int tid = threadIdx.x;
    const int L = tid & 31, wid = tid >> 5;
    const int h = blockIdx.x, b = blockIdx.y;
    const int p0w = (wid >> 1) * 64;     // warp m-offset (pixels)
    const int n0w = (wid & 1) * 64;      // warp n-offset (mid)

    // precomputed lane-invariant pieces of ldsm addresses
    const int aL = L & 15, aH = L >> 4;
    const int bR = ((L >> 4) << 3) + (L & 7), bH = (L >> 3) & 1;

    auto issue_loads = [&](int t, int buf) {
        const int dy = t >> 3, cc = t & 7;
        const unsigned Ab = sbase + buf * STG;
        const unsigned Bb = Ab + A_ST;
        const __half* asrc = g_ft + ((size_t)(b * HP + h + dy) * WP) * CIN + cc * 32;
#pragma unroll
        for (int i = 0; i < 5; i++) {            // A: 258 rows x 4 chunks = 1032
            int g = tid + i * 256;
            if (g < 1032) {
                int row = g >> 2, c = g & 3;
                cp16(Ab + swz64(row, c), asrc + (size_t)row * CIN + c * 8);
            }
        }
        const __half* bsrc = g_w1h + (size_t)((dy * 8 + cc) * 3) * MID * 32;
#pragma unroll
        for (int i = 0; i < 6; i++) {            // B: 3 x 128 rows x 4 chunks
            int g = tid + i * 256;
            int dxi = g >> 9, row = (g >> 2) & 127, c = g & 3;
            cp16(Bb + dxi * 8192 + swz64(row, c),
                 bsrc + (size_t)dxi * MID * 32 + row * 32 + c * 8);
        }
        asm volatile("cp.async.commit_group;");
    };

    float acc[4][8][4];
#pragma unroll
    for (int mi = 0; mi < 4; mi++)
#pragma unroll
        for (int ni = 0; ni < 8; ni++)
#pragma unroll
            for (int q = 0; q < 4; q++) acc[mi][ni][q] = 0.f;

    issue_loads(0, 0);
    issue_loads(1, 1);
    issue_loads(2, 2);

    unsigned afr[2][4][4], bfr[2][4][4];

    for (int t = 0; t < 24; t++) {
        const int buf = t & (NSTG - 1);
        if (t < 22)       asm volatile("cp.async.wait_group 2;");
        else if (t == 22) asm volatile("cp.async.wait_group 1;");
        else              asm volatile("cp.async.wait_group 0;");
        __syncthreads();
        if (t < 21) issue_loads(t + 3, (t + 3) & (NSTG - 1));

        const unsigned Ab = sbase + buf * STG;
        const unsigned Bb = Ab + A_ST;

        // group g = (dx, kk): dx = g>>1, kk = g&1
        // prologue: load group 0 into buffer 0
#pragma unroll
        for (int mi = 0; mi < 4; mi++) {
            int row = p0w + mi * 16 + aL;        // dx = 0
            ldsm4(afr[0][mi], Ab + swz64(row, aH));
        }
#pragma unroll
        for (int jj = 0; jj < 4; jj++) {
            int row = n0w + jj * 16 + bR;
            ldsm4(bfr[0][jj], Bb + swz64(row, bH));
        }

#pragma unroll
        for (int g = 0; g < 6; g++) {
            const int pb = g & 1;
            if (g < 5) {                         // prefetch group g+1
                const int dx2 = (g + 1) >> 1, kk2 = (g + 1) & 1;
#pragma unroll
                for (int mi = 0; mi < 4; mi++) {
                    int row = p0w + mi * 16 + aL + dx2;
                    ldsm4(afr[pb ^ 1][mi], Ab + swz64(row, 2 * kk2 + aH));
                }
#pragma unroll
                for (int jj = 0; jj < 4; jj++) {
                    int row = n0w + jj * 16 + bR;
                    ldsm4(bfr[pb ^ 1][jj],
                          Bb + dx2 * 8192 + swz64(row, 2 * kk2 + bH));
                }
            }
#pragma unroll
            for (int mi = 0; mi < 4; mi++)
#pragma unroll
                for (int ni = 0; ni < 8; ni++)
                    mma16816(acc[mi][ni], afr[pb][mi],
                             &bfr[pb][ni >> 1][(ni & 1) << 1]);
        }
    }

    // Epilogue: BN + ReLU -> g_xh[b][pixel][mid] fp16
    const int midb = n0w + ((L & 3) << 1);
    float iv0[8], iv1[8], bb0[8], bb1[8];
#pragma unroll
    for (int ni = 0; ni < 8; ni++) {
        int m0 = midb + ni * 8;
        iv0[ni] = gamma[m0]     * rsqrtf(var[m0]     + EPSBN);
        iv1[ni] = gamma[m0 + 1] * rsqrtf(var[m0 + 1] + EPSBN);
        bb0[ni] = beta[m0]     - mean[m0]     * iv0[ni];
        bb1[ni] = beta[m0 + 1] - mean[m0 + 1] * iv1[ni];
    }
#pragma unroll
    for (int mi = 0; mi < 4; mi++) {
        int p0 = p0w + mi * 16 + (L >> 2);
        __half* o = g_xh + ((size_t)b * HW + (size_t)h * Ww + p0) * MID;
#pragma unroll
        for (int ni = 0; ni < 8; ni++) {
            int m0 = midb + ni * 8;
            float u0 = fmaxf(fmaf(acc[mi][ni][0], iv0[ni], bb0[ni]), 0.f);
            float u1 = fmaxf(fmaf(acc[mi][ni][1], iv1[ni], bb1[ni]), 0.f);
            float u2 = fmaxf(fmaf(acc[mi][ni][2], iv0[ni], bb0[ni]), 0.f);
            float u3 = fmaxf(fmaf(acc[mi][ni][3], iv1[ni], bb1[ni]), 0.f);
            *(__half2*)(o + m0)           = __floats2half2_rn(u0, u1);
            *(__half2*)(o + 8 * MID + m0) = __floats2half2_rn(u2, u3);
        }
    }
}

// ---------------------------------------------------------------------------
// Kernel 2: conv1x1 as fp16 mma GEMM + bias + softmax over 4 dirs.
// ---------------------------------------------------------------------------
#define C1_A   65536                 // 256 rows x 256B
#define C1_B   20480                 // 80 rows x 256B
#define C1SMEM (C1_A + C1_B)

static __device__ __forceinline__ unsigned swz256(int row, int ch) {
    return row * 256 + ((ch & 8) << 4) + (((ch & 7) ^ (row & 7)) << 4);
}

__global__ void __launch_bounds__(256) conv1x1_mma_softmax_kernel(
    const float* __restrict__ b2)
{
    extern __shared__ __align__(1024) unsigned char smem_raw[];
    const unsigned sA = smem_u32(smem_raw);
    const unsigned sB = sA + C1_A;
    const int tid = threadIdx.x;
    const int L = tid & 31, wid = tid >> 5;
    const int p0 = blockIdx.x * 256, b = blockIdx.y;

    const __half* xsrc = g_xh + ((size_t)b * HW + p0) * MID;
#pragma unroll
    for (int i = 0; i < 16; i++) {               // A: 256 rows x 16 chunks
        int g = tid + i * 256;
        int row = g >> 4, c = g & 15;
        cp16(sA + swz256(row, c), xsrc + (size_t)row * MID + c * 8);
    }
#pragma unroll
    for (int i = 0; i < 5; i++) {                // B: 80 rows x 16 chunks
        int g = tid + i * 256;
        int row = g >> 4, c = g & 15;
        cp16(sB + swz256(row, c), g_w2h + (size_t)row * MID + c * 8);
    }
    asm volatile("cp.async.commit_group;");
    asm volatile("cp.async.wait_group 0;");
    __syncthreads();

    const int pw = wid * 32;
    float acc[2][10][4];
#pragma unroll
    for (int mi = 0; mi < 2; mi++)
#pragma unroll
        for (int ni = 0; ni < 10; ni++)
#pragma unroll
            for (int q = 0; q < 4; q++) acc[mi][ni][q] = 0.f;

#pragma unroll
    for (int kk = 0; kk < 8; kk++) {
        unsigned a[2][4], bf[5][4];
#pragma unroll
        for (int mi = 0; mi < 2; mi++) {
            int row = pw + mi * 16 + (L & 15);
            ldsm4(a[mi], sA + swz256(row, 2 * kk + (L >> 4)));
        }
#pragma unroll
        for (int jj = 0; jj < 5; jj++) {
            int row = jj * 16 + ((L >> 4) << 3) + (L & 7);
            ldsm4(bf[jj], sB + swz256(row, 2 * kk + ((L >> 3) & 1)));
        }
#pragma unroll
        for (int mi = 0; mi < 2; mi++)
#pragma unroll
            for (int ni = 0; ni < 10; ni++)
                mma16816(acc[mi][ni], a[mi], &bf[ni >> 1][(ni & 1) << 1]);
    }

    const int d0 = (L & 1) * 2;
#pragma unroll
    for (int mi = 0; mi < 2; mi++) {
#pragma unroll
        for (int h2 = 0; h2 < 2; h2++) {
            int px = p0 + pw + mi * 16 + (L >> 2) + h2 * 8;
#pragma unroll
            for (int ni = 0; ni < 10; ni++) {
                int n0 = 8 * ni + 2 * (L & 3);
                bool valid = (n0 < 76);
                float bb0 = valid ? b2[n0] : 0.f;
                float bb1 = valid ? b2[n0 + 1] : 0.f;
                float v0 = acc[mi][ni][2 * h2]     + bb0;
                float v1 = acc[mi][ni][2 * h2 + 1] + bb1;
                float p0v = __shfl_xor_sync(0xFFFFFFFFu, v0, 1);
                float p1v = __shfl_xor_sync(0xFFFFFFFFu, v1, 1);
                float mx = fmaxf(fmaxf(v0, v1), fmaxf(p0v, p1v));
                float e0 = expf(v0 - mx), e1 = expf(v1 - mx);
                float ep0 = expf(p0v - mx), ep1 = expf(p1v - mx);
                float inv = 1.f / (e0 + e1 + ep0 + ep1);
                if (valid) {
                    int k = n0 >> 2;
                    float2 r; r.x = e0 * inv; r.y = e1 * inv;
                    *(float2*)(g_g + (((size_t)b * Kk + k) * HW + px) * 4 + d0) = r;
                }
            }
        }
    }
}

// ---------------------------------------------------------------------------
// Kernel 3: all 4 propagation steps fused; 32x32 output tile + halo 4.
// ---------------------------------------------------------------------------
#define TR 40                         // loaded region 40x40

template<int S>
static __device__ __forceinline__ void prop_step_smem(
    const float* __restrict__ src, float* __restrict__ dst,
    const float* __restrict__ sg, int tid)
{
    const int n = TR - 2 * S;
    for (int q = tid; q < n * n; q += 256) {
        int r = S + q / n, c = S + q % n;
        int id = r * TR + c;
        float4 gv = *(const float4*)(sg + id * 4);
        float hc = src[id];
        float l = src[id - 1], rr = src[id + 1];
        float u = src[id - TR], d = src[id + TR];
        float selfw = 1.f - (gv.x + gv.y + gv.z + gv.w);
        dst[id] = selfw * hc + gv.x * l + gv.y * rr + gv.z * u + gv.w * d;
    }
}

__global__ __launch_bounds__(256) void prop_fused_kernel(
    const float* __restrict__ logits, float* __restrict__ h_out)
{
    __shared__ float sg[TR * TR * 4];
    __shared__ float sh[2][TR * TR];

    const int tid = threadIdx.x;
    const int wo = blockIdx.x * 32, ho = blockIdx.y * 32;
    const int plane = blockIdx.z;
    const float* hsrc = logits + (size_t)plane * HW;
    const float* gsrc = g_g + (size_t)plane * HW * 4;

    for (int q = tid; q < TR * TR; q += 256) {
        int r = q / TR, c = q % TR;
        int gr = ho + r - 4, gc = wo + c - 4;
        bool in = ((unsigned)gr < (unsigned)Hh) && ((unsigned)gc < (unsigned)Ww);
        float4 gv = make_float4(0.f, 0.f, 0.f, 0.f);
        float hv = 0.f;
        if (in) {
            gv = *(const float4*)(gsrc + ((size_t)gr * Ww + gc) * 4);
            hv = hsrc[(size_t)gr * Ww + gc];
        }
        *(float4*)(sg + q * 4) = gv;
        sh[0][q] = hv;
    }
    __syncthreads();

    prop_step_smem<1>(sh[0], sh[1], sg, tid);
    __syncthreads();
    prop_step_smem<2>(sh[1], sh[0], sg, tid);
    __syncthreads();
    prop_step_smem<3>(sh[0], sh[1], sg, tid);
    __syncthreads();

    const float* src = sh[1];
    for (int q = tid; q < 32 * 32; q += 256) {
        int r = 4 + (q >> 5), c = 4 + (q & 31);
        int id = r * TR + c;
        float4 gv = *(const float4*)(sg + id * 4);
        float hc = src[id];
        float l = src[id - 1], rr = src[id + 1];
        float u = src[id - TR], d = src[id + TR];
        float selfw = 1.f - (gv.x + gv.y + gv.z + gv.w);
        float res = selfw * hc + gv.x * l + gv.y * rr + gv.z * u + gv.w * d;
        h_out[(size_t)plane * HW + (size_t)(ho + r - 4) * Ww + (wo + c - 4)] = res;
    }
}

// ---------------------------------------------------------------------------
// kernel_launch
// inputs: 0 feats, 1 logits, 2 w1, 3 gamma, 4 beta, 5 mean, 6 var, 7 w2, 8 b2
// ---------------------------------------------------------------------------
extern "C" void kernel_launch(void* const* d_in, const int* in_sizes, int n_in,
                              void* d_out, int out_size)
{
    const float* feats  = (const float*)d_in[0];
    const float* logits = (const float*)d_in[1];
    const float* w1     = (const float*)d_in[2];
    const float* gamma  = (const float*)d_in[3];
    const float* beta   = (const float*)d_in[4];
    const float* mean   = (const float*)d_in[5];
    const float* var    = (const float*)d_in[6];
    const float* w2     = (const float*)d_in[7];
    const float* b2     = (const float*)d_in[8];
    float* out = (float*)d_out;

    cudaFuncSetAttribute(conv3x3_mma_kernel,
                         cudaFuncAttributeMaxDynamicSharedMemorySize, CSMEM);
    cudaFuncSetAttribute(conv1x1_mma_softmax_kernel,
                         cudaFuncAttributeMaxDynamicSharedMemorySize, C1SMEM);

    transpose_pad_kernel<<<dim3(HP, B_), dim3(32, 8)>>>(feats);
    prep_w1h_kernel<<<(9 * MID * CIN + 255) / 256, 256>>>(w1);
    prep_w2h_kernel<<<(80 * MID + 255) / 256, 256>>>(w2);
    conv3x3_mma_kernel<<<dim3(Hh, B_), 256, CSMEM>>>(gamma, beta, mean, var);
    conv1x1_mma_softmax_kernel<<<dim3(HW / 256, B_), 256, C1SMEM>>>(b2);
    prop_fused_kernel<<<dim3(Ww / 32, Hh / 32, B_ * Kk), 256>>>(logits, out);
}